// round 15
// baseline (speedup 1.0000x reference)
#include <cuda_runtime.h>
#include <cuda_fp16.h>
#include <cstdint>

// ---------------- problem constants ----------------
#define YTRUE_OFF  33505280l
#define YTRUE_SIZE 261760l
#define ACC_OFF    33767040l

// ---------------- scratch (__device__ globals; no allocs allowed) ----------------
static __device__ __half g_ts16[128ll * 1024 * 512];        // timesteps f16 [n][l][c]
static __device__ __half g_pt16[128ll * 1024 * 512];        // patient f16 [m][l][c]
static __device__ __half g_w16[2ll * 512 * 512];            // W1,W2 f16
static __device__ float  g_lneg[2045ll * 128 * 128];        // [gl][n*128+m]
static __device__ unsigned int g_cnt[2];

// ---------------- PTX helpers ----------------
__device__ __forceinline__ uint32_t s2u(const void* p) {
    uint32_t a;
    asm("{ .reg .u64 t; cvta.to.shared.u64 t, %1; cvt.u32.u64 %0, t; }" : "=r"(a) : "l"(p));
    return a;
}
__device__ __forceinline__ void cp16(uint32_t dst, const void* src) {
    asm volatile("cp.async.cg.shared.global [%0], [%1], 16;" :: "r"(dst), "l"(src));
}
#define CP_COMMIT() asm volatile("cp.async.commit_group;" ::: "memory")
#define CP_WAIT1()  asm volatile("cp.async.wait_group 1;" ::: "memory")
#define CP_WAIT0()  asm volatile("cp.async.wait_group 0;" ::: "memory")

__device__ __forceinline__ void ldsm4(uint32_t addr, uint32_t& r0, uint32_t& r1,
                                      uint32_t& r2, uint32_t& r3) {
    asm volatile("ldmatrix.sync.aligned.m8n8.x4.shared.b16 {%0,%1,%2,%3}, [%4];"
                 : "=r"(r0), "=r"(r1), "=r"(r2), "=r"(r3) : "r"(addr));
}
__device__ __forceinline__ void mma16816(float* d, const uint32_t* a, uint32_t b0, uint32_t b1) {
    asm volatile(
        "mma.sync.aligned.m16n8k16.row.col.f32.f16.f16.f32 "
        "{%0,%1,%2,%3}, {%4,%5,%6,%7}, {%8,%9}, {%0,%1,%2,%3};"
        : "+f"(d[0]), "+f"(d[1]), "+f"(d[2]), "+f"(d[3])
        : "r"(a[0]), "r"(a[1]), "r"(a[2]), "r"(a[3]), "r"(b0), "r"(b1));
}

// ---------------- fused-kernel smem geometry ----------------
#define ROWB    144u                 // 64 halves + 16B pad
#define MATB    (128u * ROWB)        // 18432
#define STB     (2u * MATB)          // 36864 (A+B per GEMM1 stage)
#define R1_OFF  0u                   // 3 stages: 110592
#define A2_OFF  110592u              // 2 parity sets x 2 tiles: 73728
#define T1_OFF  184320u              // 128 x 272B = 34816
#define T1ROWB  272u                 // 128 halves + 16B pad
#define FSMEM   219136u

// ---------------- compute fragment: warp tile 32x32 ----------------
__device__ __forceinline__ void compute32(uint32_t Ab, uint32_t sA, uint32_t Bb, uint32_t sB,
                                          uint32_t kbase, int wm, int wn, int lane,
                                          float acc[2][4][4]) {
    const uint32_t rlane = (uint32_t)(((lane >> 3) & 1) * 8 + (lane & 7));
    const uint32_t koffl = (uint32_t)(((lane >> 4) & 1) * 16);
#pragma unroll
    for (int kk = 0; kk < 4; kk++) {
        const uint32_t kb = (uint32_t)kk * 32u + koffl;
        uint32_t a[2][4];
#pragma unroll
        for (int mt = 0; mt < 2; mt++)
            ldsm4(Ab + ((uint32_t)(wm * 32 + mt * 16) + rlane) * sA + kb,
                  a[mt][0], a[mt][1], a[mt][2], a[mt][3]);
        uint32_t b[2][4];
#pragma unroll
        for (int p = 0; p < 2; p++)
            ldsm4(Bb + ((uint32_t)(wn * 32 + p * 16) + rlane) * sB + kbase + kb,
                  b[p][0], b[p][1], b[p][2], b[p][3]);
#pragma unroll
        for (int mt = 0; mt < 2; mt++)
#pragma unroll
            for (int nt = 0; nt < 4; nt++)
                mma16816(acc[mt][nt], a[mt], b[nt >> 1][nt & 1], b[nt >> 1][2 + (nt & 1)]);
    }
}

// ---------------- prologue (one launch) ----------------
__device__ __forceinline__ void cvt_body(const float* __restrict__ src, __half* __restrict__ dst,
                                         long i, long stride, long n4) {
    for (; i < n4; i += stride) {
        float4 v = ((const float4*)src)[i];
        __half2 h0 = __floats2half2_rn(v.x, v.y);
        __half2 h1 = __floats2half2_rn(v.z, v.w);
        uint2 u;
        u.x = *reinterpret_cast<unsigned*>(&h0);
        u.y = *reinterpret_cast<unsigned*>(&h1);
        ((uint2*)dst)[i] = u;
    }
}

__global__ void k_cvt_all(const float* __restrict__ ts, const float* __restrict__ pt,
                          const float* __restrict__ W1, const float* __restrict__ W2,
                          float* __restrict__ out) {
    const long n4 = 128l * 1024 * 512 / 4;
    const int tid = threadIdx.x;
    if (blockIdx.z == 0) {
        cvt_body(ts, g_ts16, (long)blockIdx.x * 256 + tid, 16384l * 256, n4);
    } else if (blockIdx.z == 1) {
        cvt_body(pt, g_pt16, (long)blockIdx.x * 256 + tid, 16384l * 256, n4);
    } else {
        long x = blockIdx.x;
        if (x < 512) {
            long i = x * 256 + tid;
            const float* src = (i < 65536) ? W1 : W2;
            __half* dst = g_w16 + ((i < 65536) ? 0l : 262144l);
            long j = i & 65535;
            float4 v = ((const float4*)src)[j];
            __half2 h0 = __floats2half2_rn(v.x, v.y);
            __half2 h1 = __floats2half2_rn(v.z, v.w);
            uint2 u;
            u.x = *reinterpret_cast<unsigned*>(&h0);
            u.y = *reinterpret_cast<unsigned*>(&h1);
            ((uint2*)dst)[j] = u;
        } else if (x < 1536) {
            long idx = (x - 512) * 256 + tid;
            if (idx < YTRUE_SIZE) out[YTRUE_OFF + idx] = (float)(idx / 2045);
        } else if (x == 1536) {
            if (tid < 2) g_cnt[tid] = 0u;
        }
    }
}

__global__ void k_accs(float* __restrict__ out) {
    if (threadIdx.x == 0) out[ACC_OFF + 0] = (float)g_cnt[0] * (1.0f / (128.0f * 1023.0f));
    if (threadIdx.x == 1) out[ACC_OFF + 1] = (float)g_cnt[1] * (1.0f / (128.0f * 1022.0f));
}

// ---------------- k_fused: per (l,step) CTA — pred tile + lneg, no pred16 round-trip ----------------
// 512 thr, 16 warps (grid 4x4, warp tile 32x32).
// GEMM1 (x4 c-blocks): T1[m][c] = P[m,l,:]·W_cb + b_cb   (K=512, 8 ktiles, global 3-stage ring)
// GEMM2 (per cb):      D[n][m] += ts[n,l+s,cb-range]·T1^T (2 ktiles, B from smem T1)
__global__ __launch_bounds__(512, 1) void k_fused(const float* __restrict__ b1,
                                                  const float* __restrict__ b2) {
    extern __shared__ char dsm[];
    __shared__ float sb[512];
    const int tid = threadIdx.x;
    const int l = blockIdx.x;
    const int step = blockIdx.y;
    if (l >= 1023 - step) return;
    const int lane = tid & 31, wid = tid >> 5, wm = wid & 3, wn = wid >> 2;
    const uint32_t base = s2u(dsm);
    const float* bias = step ? b2 : b1;

    sb[tid] = bias[tid];

    // per-thread copy roles: rows r0, r0+64; 16B segment seg
    const int r0 = tid >> 3;
    const uint32_t seg = (uint32_t)(tid & 7) * 16u;
    const __half* pA[2]; const __half* pB[2]; const __half* pT[2];
#pragma unroll
    for (int i = 0; i < 2; i++) {
        int r = r0 + 64 * i;
        pA[i] = g_pt16 + ((long)r * 1024 + l) * 512 + (tid & 7) * 8;                     // P rows m
        pB[i] = g_w16 + (long)step * 262144 + (long)r * 512 + (tid & 7) * 8;             // W rows c
        pT[i] = g_ts16 + ((long)r * 1024 + (l + step + 1)) * 512 + (tid & 7) * 8;        // ts rows n
    }

    // issue GEMM1 stage g (g = cb*8+kt): A tile (P, k-range kt) + B tile (W rows cb*128.., k-range kt)
    auto issueG1 = [&](int g) {
        int cb = g >> 3, kt = g & 7;
        uint32_t sbuf = base + R1_OFF + (uint32_t)(g % 3) * STB;
        int koff = kt * 64;
#pragma unroll
        for (int i = 0; i < 2; i++) {
            uint32_t r = (uint32_t)(r0 + 64 * i);
            cp16(sbuf + r * ROWB + seg, pA[i] + koff);
            cp16(sbuf + MATB + r * ROWB + seg, pB[i] + (cb << 16) + koff);
        }
    };
    // issue GEMM2 A tile j for cb (ts rows n, c-range cb*128 + j*64), parity-buffered
    auto issueA2 = [&](int cb, int j) {
        uint32_t dbuf = base + A2_OFF + (uint32_t)(cb & 1) * STB + (uint32_t)j * MATB;
#pragma unroll
        for (int i = 0; i < 2; i++) {
            uint32_t r = (uint32_t)(r0 + 64 * i);
            cp16(dbuf + r * ROWB + seg, pT[i] + cb * 128 + j * 64);
        }
    };

    issueG1(0); CP_COMMIT();
    issueG1(1); CP_COMMIT();

    float acc2[2][4][4] = {};
    for (int cb = 0; cb < 4; cb++) {
        float acc1[2][4][4] = {};
#pragma unroll
        for (int kt = 0; kt < 8; kt++) {
            const int g = cb * 8 + kt;
            if (g < 31) CP_WAIT1(); else CP_WAIT0();
            __syncthreads();
            if (g + 2 < 32) {
                issueG1(g + 2);
                if (kt == 0) { issueA2(cb, 0); issueA2(cb, 1); }
                CP_COMMIT();
            } else if (kt == 0) {        // cb==3 late A2 (g+2 >= 32 never happens for kt==0; keep safe)
                issueA2(cb, 0); issueA2(cb, 1); CP_COMMIT();
            }
            uint32_t sbuf = base + R1_OFF + (uint32_t)(g % 3) * STB;
            compute32(sbuf, ROWB, sbuf + MATB, ROWB, 0, wm, wn, lane, acc1);
        }

        // epilogue1: acc1 + bias -> T1 (f16). Warp-private rows => no sync needed before.
        {
            const uint32_t T1 = base + T1_OFF;
#pragma unroll
            for (int mt = 0; mt < 2; mt++) {
                uint32_t mrow = (uint32_t)(wm * 32 + mt * 16 + (lane >> 2));
#pragma unroll
                for (int nt = 0; nt < 4; nt++) {
                    int cl = wn * 32 + nt * 8 + (lane & 3) * 2;
                    int gc = cb * 128 + cl;
                    __half2 h01 = __floats2half2_rn(acc1[mt][nt][0] + sb[gc],
                                                    acc1[mt][nt][1] + sb[gc + 1]);
                    __half2 h23 = __floats2half2_rn(acc1[mt][nt][2] + sb[gc],
                                                    acc1[mt][nt][3] + sb[gc + 1]);
                    asm volatile("st.shared.b32 [%0], %1;" ::
                        "r"(T1 + mrow * T1ROWB + (uint32_t)cl * 2),
                        "r"(*reinterpret_cast<uint32_t*>(&h01)) : "memory");
                    asm volatile("st.shared.b32 [%0], %1;" ::
                        "r"(T1 + (mrow + 8) * T1ROWB + (uint32_t)cl * 2),
                        "r"(*reinterpret_cast<uint32_t*>(&h23)) : "memory");
                }
            }
        }
        __syncthreads();   // T1 visible to all warps

        // GEMM2: 2 ktiles, A = A2 parity bufs (smem), B = T1
        {
            uint32_t a2 = base + A2_OFF + (uint32_t)(cb & 1) * STB;
            uint32_t T1 = base + T1_OFF;
            compute32(a2, ROWB, T1, T1ROWB, 0, wm, wn, lane, acc2);
            compute32(a2 + MATB, ROWB, T1, T1ROWB, 128, wm, wn, lane, acc2);
        }
        __syncthreads();   // T1/A2 consumed before next cb overwrites
    }

    // epilogue2: stage D in smem (overlays ring bufs; all drained), accuracy + scratch write
    float* sC = (float*)dsm;  // [128][129]
#pragma unroll
    for (int mt = 0; mt < 2; mt++) {
        int n = wm * 32 + mt * 16 + (lane >> 2);
#pragma unroll
        for (int nt = 0; nt < 4; nt++) {
            int mc = wn * 32 + nt * 8 + (lane & 3) * 2;
            sC[n * 129 + mc]           = acc2[mt][nt][0];
            sC[n * 129 + mc + 1]       = acc2[mt][nt][1];
            sC[(n + 8) * 129 + mc]     = acc2[mt][nt][2];
            sC[(n + 8) * 129 + mc + 1] = acc2[mt][nt][3];
        }
    }
    __syncthreads();

    if (tid < 128) {
        float pos = sC[tid * 129 + tid];
        bool win = true;
#pragma unroll 8
        for (int mm = 0; mm < 128; mm++)
            if (mm != tid && !(pos > sC[tid * 129 + mm])) win = false;
        unsigned bal = __ballot_sync(0xffffffffu, win);
        if ((tid & 31) == 0) atomicAdd(&g_cnt[step], (unsigned)__popc(bal));
    }

    const float invT = 1.0f / 0.07f;
    const long gl = (long)step * 1023 + l;
    for (int idx = tid; idx < 128 * 128; idx += 512) {
        int n = idx >> 7, mm = idx & 127;
        g_lneg[gl * 16384 + idx] = sC[n * 129 + mm] * invT;
    }
}

// ---------------- k_tr: scratch [gl][nm] -> out [nm][gl] ----------------
__global__ __launch_bounds__(256) void k_tr(float* __restrict__ out) {
    __shared__ float t[32][257];
    const int tid = threadIdx.x;
    const int nm0 = blockIdx.x * 256;
    const int gl0 = blockIdx.y * 32;
#pragma unroll 4
    for (int i = 0; i < 32; i++) {
        int gl = gl0 + i;
        if (gl < 2045) t[i][tid] = g_lneg[(long)gl * 16384 + nm0 + tid];
    }
    __syncthreads();
    const int w = tid >> 5, lane = tid & 31;
    const int gl = gl0 + lane;
    if (gl < 2045) {
#pragma unroll 4
        for (int q = 0; q < 32; q++) {
            int nm = w * 32 + q;
            out[(long)(nm0 + nm) * 2045 + gl] = t[lane][nm];
        }
    }
}

// ---------------- launch ----------------
extern "C" void kernel_launch(void* const* d_in, const int* in_sizes, int n_in,
                              void* d_out, int out_size) {
    const float* ts = (const float*)d_in[0];
    const float* pt = (const float*)d_in[1];
    const float* W1 = (const float*)d_in[2];
    const float* b1 = (const float*)d_in[3];
    const float* W2 = (const float*)d_in[4];
    const float* b2 = (const float*)d_in[5];
    float* out = (float*)d_out;

    cudaFuncSetAttribute(k_fused, cudaFuncAttributeMaxDynamicSharedMemorySize, FSMEM);

    // prologue: ts cvt (z=0), pt cvt (z=1), W cvt + ytrues + zero (z=2)
    k_cvt_all<<<dim3(16384, 1, 3), 256>>>(ts, pt, W1, W2, out);

    k_fused<<<dim3(1023, 2), 512, FSMEM>>>(b1, b2);
    k_tr<<<dim3(64, 64), 256>>>(out);

    k_accs<<<1, 32>>>(out);
}

// round 16
// speedup vs baseline: 1.1170x; 1.1170x over previous
#include <cuda_runtime.h>
#include <cuda_fp16.h>
#include <cstdint>

// ---------------- problem constants ----------------
#define YTRUE_OFF  33505280l
#define YTRUE_SIZE 261760l
#define ACC_OFF    33767040l

// ---------------- scratch (__device__ globals; no allocs allowed) ----------------
static __device__ __half g_ts16[128ll * 1024 * 512];        // timesteps f16 [n][l][c]
static __device__ __half g_pt16[128ll * 1024 * 512];        // patient f16 [m][l][c]
static __device__ __half g_pred16[2ll * 1024 * 128 * 512];  // pred f16 [step][l][m][c]
static __device__ __half g_w16[2ll * 512 * 512];            // W1,W2 f16
static __device__ float  g_lneg[2045ll * 128 * 128];        // [gl][n*128+m]
static __device__ unsigned int g_cnt[2];

// ---------------- PTX helpers (family-portable; no tcgen05) ----------------
__device__ __forceinline__ uint32_t s2u(const void* p) {
    uint32_t a;
    asm("{ .reg .u64 t; cvta.to.shared.u64 t, %1; cvt.u32.u64 %0, t; }" : "=r"(a) : "l"(p));
    return a;
}
__device__ __forceinline__ void cp16(uint32_t dst, const void* src) {
    asm volatile("cp.async.cg.shared.global [%0], [%1], 16;" :: "r"(dst), "l"(src));
}
#define CP_COMMIT() asm volatile("cp.async.commit_group;" ::: "memory")
#define CP_WAIT1()  asm volatile("cp.async.wait_group 1;" ::: "memory")
#define CP_WAIT0()  asm volatile("cp.async.wait_group 0;" ::: "memory")

__device__ __forceinline__ void ldsm4(uint32_t addr, uint32_t& r0, uint32_t& r1,
                                      uint32_t& r2, uint32_t& r3) {
    asm volatile("ldmatrix.sync.aligned.m8n8.x4.shared.b16 {%0,%1,%2,%3}, [%4];"
                 : "=r"(r0), "=r"(r1), "=r"(r2), "=r"(r3) : "r"(addr));
}
__device__ __forceinline__ void mma16816(float* d, const uint32_t* a, uint32_t b0, uint32_t b1) {
    asm volatile(
        "mma.sync.aligned.m16n8k16.row.col.f32.f16.f16.f32 "
        "{%0,%1,%2,%3}, {%4,%5,%6,%7}, {%8,%9}, {%0,%1,%2,%3};"
        : "+f"(d[0]), "+f"(d[1]), "+f"(d[2]), "+f"(d[3])
        : "r"(a[0]), "r"(a[1]), "r"(a[2]), "r"(a[3]), "r"(b0), "r"(b1));
}

// ---------------- stage geometry ----------------
#define ROWB   144u                  // 64 halves + 16B pad
#define MATB   (128u * ROWB)         // 18432
#define STB    (2u * MATB)           // 36864 (A+B per stage)
#define GSMEM  (3u * STB)            // 110592 -> occ 2

// ---------------- compute fragment (warp tile 32x64, 256-thr CTAs) ----------------
__device__ __forceinline__ void compute_tile(uint32_t Ab, uint32_t Bb,
                                             int wm, int wn, int lane, float acc[2][8][4]) {
    const uint32_t rlane = (uint32_t)(((lane >> 3) & 1) * 8 + (lane & 7));
    const uint32_t koffl = (uint32_t)(((lane >> 4) & 1) * 16);
#pragma unroll
    for (int kk = 0; kk < 4; kk++) {
        const uint32_t kb = (uint32_t)kk * 32u + koffl;
        uint32_t a[2][4];
#pragma unroll
        for (int mt = 0; mt < 2; mt++)
            ldsm4(Ab + (uint32_t)(wm * 32 + mt * 16) * ROWB + rlane * ROWB + kb,
                  a[mt][0], a[mt][1], a[mt][2], a[mt][3]);
        uint32_t b[4][4];
#pragma unroll
        for (int p = 0; p < 4; p++)
            ldsm4(Bb + (uint32_t)(wn * 64 + p * 16) * ROWB + rlane * ROWB + kb,
                  b[p][0], b[p][1], b[p][2], b[p][3]);
#pragma unroll
        for (int mt = 0; mt < 2; mt++)
#pragma unroll
            for (int nt = 0; nt < 8; nt++)
                mma16816(acc[mt][nt], a[mt], b[nt >> 1][nt & 1], b[nt >> 1][2 + (nt & 1)]);
    }
}

// ---------------- prologue (one launch) ----------------
__device__ __forceinline__ void cvt_body(const float* __restrict__ src, __half* __restrict__ dst,
                                         long i, long stride, long n4) {
    for (; i < n4; i += stride) {
        float4 v = ((const float4*)src)[i];
        __half2 h0 = __floats2half2_rn(v.x, v.y);
        __half2 h1 = __floats2half2_rn(v.z, v.w);
        uint2 u;
        u.x = *reinterpret_cast<unsigned*>(&h0);
        u.y = *reinterpret_cast<unsigned*>(&h1);
        ((uint2*)dst)[i] = u;
    }
}

// z=0 -> ts cvt, z=1 -> pt cvt, z=2 -> W cvt + ytrues + zero counters
__global__ void k_cvt_all(const float* __restrict__ ts, const float* __restrict__ pt,
                          const float* __restrict__ W1, const float* __restrict__ W2,
                          float* __restrict__ out) {
    const long n4 = 128l * 1024 * 512 / 4;
    const int tid = threadIdx.x;
    if (blockIdx.z == 0) {
        cvt_body(ts, g_ts16, (long)blockIdx.x * 256 + tid, 16384l * 256, n4);
    } else if (blockIdx.z == 1) {
        cvt_body(pt, g_pt16, (long)blockIdx.x * 256 + tid, 16384l * 256, n4);
    } else {
        long x = blockIdx.x;
        if (x < 512) {
            long i = x * 256 + tid;                 // 0..131071 (W1 then W2)
            const float* src = (i < 65536) ? W1 : W2;
            __half* dst = g_w16 + ((i < 65536) ? 0l : 262144l);
            long j = i & 65535;
            float4 v = ((const float4*)src)[j];
            __half2 h0 = __floats2half2_rn(v.x, v.y);
            __half2 h1 = __floats2half2_rn(v.z, v.w);
            uint2 u;
            u.x = *reinterpret_cast<unsigned*>(&h0);
            u.y = *reinterpret_cast<unsigned*>(&h1);
            ((uint2*)dst)[j] = u;
        } else if (x < 1536) {
            long idx = (x - 512) * 256 + tid;
            if (idx < YTRUE_SIZE) out[YTRUE_OFF + idx] = (float)(idx / 2045);
        } else if (x == 1536) {
            if (tid < 2) g_cnt[tid] = 0u;
        }
    }
}

// ---------------- k_pred: R7 core; z = m*2 + step so both steps' CTAs share A via L2 ----------------
// grid (4 cb, 8 l0blk, 256)
__global__ __launch_bounds__(256, 2) void k_pred(const float* __restrict__ b1,
                                                 const float* __restrict__ b2) {
    extern __shared__ char dsm[];
    __shared__ float sb[128];
    const int tid = threadIdx.x;
    const int lane = tid & 31, wid = tid >> 5, wm = wid & 3, wn = wid >> 2;
    const int cb = blockIdx.x;
    const int l0 = blockIdx.y * 128;
    const int step = blockIdx.z & 1;          // PAIRED: adjacent z = same m, both steps
    const int m = blockIdx.z >> 1;
    const uint32_t base = s2u(dsm);
    const __half* w16 = g_w16 + (long)step * 262144;
    const float* bias = step ? b2 : b1;

    if (tid < 128) sb[tid] = bias[cb * 128 + tid];

    const __half* aP[4]; const __half* bP[4];
#pragma unroll
    for (int i = 0; i < 4; i++) {
        int r = (tid >> 3) + 32 * i;
        aP[i] = g_pt16 + ((long)(m * 1024 + l0 + r)) * 512 + (tid & 7) * 8;
        bP[i] = w16 + ((long)(cb * 128 + r)) * 512 + (tid & 7) * 8;
    }
    const uint32_t seg = (uint32_t)(tid & 7) * 16u;

    auto issue = [&](int kc) {
        uint32_t sbuf = base + (uint32_t)(kc % 3) * STB;
        int koff = kc * 64;
#pragma unroll
        for (int i = 0; i < 4; i++) {
            uint32_t r = (uint32_t)(tid >> 3) + 32u * i;
            cp16(sbuf + r * ROWB + seg, aP[i] + koff);
            cp16(sbuf + MATB + r * ROWB + seg, bP[i] + koff);
        }
    };

    issue(0); CP_COMMIT();
    issue(1); CP_COMMIT();

    float acc[2][8][4] = {};
#pragma unroll
    for (int kc = 0; kc < 8; kc++) {
        if (kc < 7) CP_WAIT1(); else CP_WAIT0();
        __syncthreads();
        if (kc + 2 < 8) { issue(kc + 2); CP_COMMIT(); }
        compute_tile(base + (uint32_t)(kc % 3) * STB,
                     base + (uint32_t)(kc % 3) * STB + MATB, wm, wn, lane, acc);
    }

    // epilogue: +bias, f16 store to g_pred16[step][l0+row][m][cb*128+cl]
#pragma unroll
    for (int mt = 0; mt < 2; mt++) {
        int mrow = wm * 32 + mt * 16 + (lane >> 2);      // l within tile
        long gr = ((long)(step * 1024 + l0 + mrow)) * 128 + m;
#pragma unroll
        for (int nt = 0; nt < 8; nt++) {
            int cl = wn * 64 + nt * 8 + (lane & 3) * 2;
            __half2 h01 = __floats2half2_rn(acc[mt][nt][0] + sb[cl],
                                            acc[mt][nt][1] + sb[cl + 1]);
            *(__half2*)&g_pred16[gr * 512 + cb * 128 + cl] = h01;
            __half2 h23 = __floats2half2_rn(acc[mt][nt][2] + sb[cl],
                                            acc[mt][nt][3] + sb[cl + 1]);
            *(__half2*)&g_pred16[(gr + 8l * 128) * 512 + cb * 128 + cl] = h23;  // l+8
        }
    }
}

// ---------------- k_lneg: per-(l,step), B tile contiguous 131KB ----------------
__global__ __launch_bounds__(256, 2) void k_lneg() {
    extern __shared__ char dsm[];
    const int tid = threadIdx.x;
    const int lane = tid & 31, wid = tid >> 5, wm = wid & 3, wn = wid >> 2;
    const int l = blockIdx.x;
    const int step = blockIdx.y;             // 0 or 1
    const int LS = 1023 - step;
    if (l >= LS) return;                     // uniform per CTA
    const uint32_t base = s2u(dsm);

    const __half* aP[4]; const __half* bP[4];
#pragma unroll
    for (int i = 0; i < 4; i++) {
        int r = (tid >> 3) + 32 * i;
        aP[i] = g_ts16 + ((long)(r * 1024) + l + step + 1) * 512 + (tid & 7) * 8;          // n rows
        bP[i] = g_pred16 + (((long)(step * 1024 + l)) * 128 + r) * 512 + (tid & 7) * 8;    // m rows
    }
    const uint32_t seg = (uint32_t)(tid & 7) * 16u;

    auto issue = [&](int kc) {
        uint32_t sbuf = base + (uint32_t)(kc % 3) * STB;
        int koff = kc * 64;
#pragma unroll
        for (int i = 0; i < 4; i++) {
            uint32_t r = (uint32_t)(tid >> 3) + 32u * i;
            cp16(sbuf + r * ROWB + seg, aP[i] + koff);
            cp16(sbuf + MATB + r * ROWB + seg, bP[i] + koff);
        }
    };

    issue(0); CP_COMMIT();
    issue(1); CP_COMMIT();

    float acc[2][8][4] = {};
#pragma unroll
    for (int kc = 0; kc < 8; kc++) {
        if (kc < 7) CP_WAIT1(); else CP_WAIT0();
        __syncthreads();
        if (kc + 2 < 8) { issue(kc + 2); CP_COMMIT(); }
        compute_tile(base + (uint32_t)(kc % 3) * STB,
                     base + (uint32_t)(kc % 3) * STB + MATB, wm, wn, lane, acc);
    }
    __syncthreads();

    float* sC = (float*)dsm;  // [128][129]
#pragma unroll
    for (int mt = 0; mt < 2; mt++) {
        int n = wm * 32 + mt * 16 + (lane >> 2);
#pragma unroll
        for (int nt = 0; nt < 8; nt++) {
            int mc = wn * 64 + nt * 8 + (lane & 3) * 2;
            sC[n * 129 + mc]           = acc[mt][nt][0];
            sC[n * 129 + mc + 1]       = acc[mt][nt][1];
            sC[(n + 8) * 129 + mc]     = acc[mt][nt][2];
            sC[(n + 8) * 129 + mc + 1] = acc[mt][nt][3];
        }
    }
    __syncthreads();

    if (tid < 128) {
        float pos = sC[tid * 129 + tid];
        bool win = true;
#pragma unroll 8
        for (int mm = 0; mm < 128; mm++)
            if (mm != tid && !(pos > sC[tid * 129 + mm])) win = false;
        unsigned bal = __ballot_sync(0xffffffffu, win);
        if ((tid & 31) == 0) atomicAdd(&g_cnt[step], (unsigned)__popc(bal));
    }

    const float invT = 1.0f / 0.07f;
    const long gl = (long)step * 1023 + l;
    for (int idx = tid; idx < 128 * 128; idx += 256) {
        int n = idx >> 7, mm = idx & 127;
        g_lneg[gl * 16384 + idx] = sC[n * 129 + mm] * invT;
    }
}

// ---------------- k_tr: scratch [gl][nm] -> out [nm][gl]; block(0,0) also writes accs ----------------
__global__ __launch_bounds__(256) void k_tr(float* __restrict__ out) {
    __shared__ float t[32][257];
    const int tid = threadIdx.x;
    const int nm0 = blockIdx.x * 256;
    const int gl0 = blockIdx.y * 32;

    // fold accs (g_cnt finalized by the preceding lneg launch)
    if (blockIdx.x == 0 && blockIdx.y == 0) {
        if (tid == 0) out[ACC_OFF + 0] = (float)g_cnt[0] * (1.0f / (128.0f * 1023.0f));
        if (tid == 1) out[ACC_OFF + 1] = (float)g_cnt[1] * (1.0f / (128.0f * 1022.0f));
    }

#pragma unroll 4
    for (int i = 0; i < 32; i++) {
        int gl = gl0 + i;
        if (gl < 2045) t[i][tid] = g_lneg[(long)gl * 16384 + nm0 + tid];
    }
    __syncthreads();
    const int w = tid >> 5, lane = tid & 31;
    const int gl = gl0 + lane;
    if (gl < 2045) {
#pragma unroll 4
        for (int q = 0; q < 32; q++) {
            int nm = w * 32 + q;
            out[(long)(nm0 + nm) * 2045 + gl] = t[lane][nm];
        }
    }
}

// ---------------- launch ----------------
extern "C" void kernel_launch(void* const* d_in, const int* in_sizes, int n_in,
                              void* d_out, int out_size) {
    const float* ts = (const float*)d_in[0];
    const float* pt = (const float*)d_in[1];
    const float* W1 = (const float*)d_in[2];
    const float* b1 = (const float*)d_in[3];
    const float* W2 = (const float*)d_in[4];
    const float* b2 = (const float*)d_in[5];
    float* out = (float*)d_out;

    cudaFuncSetAttribute(k_pred, cudaFuncAttributeMaxDynamicSharedMemorySize, GSMEM);
    cudaFuncSetAttribute(k_lneg, cudaFuncAttributeMaxDynamicSharedMemorySize, GSMEM);

    // prologue: ts cvt (z=0), pt cvt (z=1), W cvt + ytrues + zero (z=2)
    k_cvt_all<<<dim3(16384, 1, 3), 256>>>(ts, pt, W1, W2, out);

    k_pred<<<dim3(4, 8, 256), 256, GSMEM>>>(b1, b2);
    k_lneg<<<dim3(1023, 2), 256, GSMEM>>>();
    k_tr<<<dim3(64, 64), 256>>>(out);   // also writes accs
}

// round 17
// speedup vs baseline: 1.1438x; 1.0241x over previous
#include <cuda_runtime.h>
#include <cuda_fp16.h>
#include <cstdint>

// ---------------- problem constants ----------------
#define YTRUE_OFF  33505280l
#define YTRUE_SIZE 261760l
#define ACC_OFF    33767040l

// ---------------- scratch (__device__ globals; no allocs allowed) ----------------
static __device__ __half g_ts16[128ll * 1024 * 512];        // timesteps f16 [n][l][c]
static __device__ __half g_pt16[128ll * 1024 * 512];        // patient f16 [m][l][c]
static __device__ __half g_pred16[2ll * 1024 * 128 * 512];  // pred f16 [step][l][m][c]
static __device__ __half g_w16[2ll * 512 * 512];            // W1,W2 f16
static __device__ float  g_lneg[2045ll * 128 * 128];        // [gl][n*128+m]
static __device__ unsigned int g_cnt[2];

// ---------------- PTX helpers (family-portable; no tcgen05) ----------------
__device__ __forceinline__ uint32_t s2u(const void* p) {
    uint32_t a;
    asm("{ .reg .u64 t; cvta.to.shared.u64 t, %1; cvt.u32.u64 %0, t; }" : "=r"(a) : "l"(p));
    return a;
}
__device__ __forceinline__ void cp16(uint32_t dst, const void* src) {
    asm volatile("cp.async.cg.shared.global [%0], [%1], 16;" :: "r"(dst), "l"(src));
}
#define CP_COMMIT() asm volatile("cp.async.commit_group;" ::: "memory")
#define CP_WAIT1()  asm volatile("cp.async.wait_group 1;" ::: "memory")
#define CP_WAIT0()  asm volatile("cp.async.wait_group 0;" ::: "memory")

__device__ __forceinline__ void ldsm4(uint32_t addr, uint32_t& r0, uint32_t& r1,
                                      uint32_t& r2, uint32_t& r3) {
    asm volatile("ldmatrix.sync.aligned.m8n8.x4.shared.b16 {%0,%1,%2,%3}, [%4];"
                 : "=r"(r0), "=r"(r1), "=r"(r2), "=r"(r3) : "r"(addr));
}
__device__ __forceinline__ void mma16816(float* d, const uint32_t* a, uint32_t b0, uint32_t b1) {
    asm volatile(
        "mma.sync.aligned.m16n8k16.row.col.f32.f16.f16.f32 "
        "{%0,%1,%2,%3}, {%4,%5,%6,%7}, {%8,%9}, {%0,%1,%2,%3};"
        : "+f"(d[0]), "+f"(d[1]), "+f"(d[2]), "+f"(d[3])
        : "r"(a[0]), "r"(a[1]), "r"(a[2]), "r"(a[3]), "r"(b0), "r"(b1));
}

// ---------------- stage geometry ----------------
#define ROWB   144u                  // 64 halves + 16B pad
#define MATB   (128u * ROWB)         // 18432
#define STB    (2u * MATB)           // 36864 (A+B per stage)
#define GSMEM  (3u * STB)            // 110592 -> occ 2

// ---------------- compute fragment (warp tile 32x64, 256-thr CTAs) ----------------
__device__ __forceinline__ void compute_tile(uint32_t Ab, uint32_t Bb,
                                             int wm, int wn, int lane, float acc[2][8][4]) {
    const uint32_t rlane = (uint32_t)(((lane >> 3) & 1) * 8 + (lane & 7));
    const uint32_t koffl = (uint32_t)(((lane >> 4) & 1) * 16);
#pragma unroll
    for (int kk = 0; kk < 4; kk++) {
        const uint32_t kb = (uint32_t)kk * 32u + koffl;
        uint32_t a[2][4];
#pragma unroll
        for (int mt = 0; mt < 2; mt++)
            ldsm4(Ab + (uint32_t)(wm * 32 + mt * 16) * ROWB + rlane * ROWB + kb,
                  a[mt][0], a[mt][1], a[mt][2], a[mt][3]);
        uint32_t b[4][4];
#pragma unroll
        for (int p = 0; p < 4; p++)
            ldsm4(Bb + (uint32_t)(wn * 64 + p * 16) * ROWB + rlane * ROWB + kb,
                  b[p][0], b[p][1], b[p][2], b[p][3]);
#pragma unroll
        for (int mt = 0; mt < 2; mt++)
#pragma unroll
            for (int nt = 0; nt < 8; nt++)
                mma16816(acc[mt][nt], a[mt], b[nt >> 1][nt & 1], b[nt >> 1][2 + (nt & 1)]);
    }
}

// ---------------- prologue (one launch) ----------------
__device__ __forceinline__ void cvt_body(const float* __restrict__ src, __half* __restrict__ dst,
                                         long i, long stride, long n4) {
    for (; i < n4; i += stride) {
        float4 v = ((const float4*)src)[i];
        __half2 h0 = __floats2half2_rn(v.x, v.y);
        __half2 h1 = __floats2half2_rn(v.z, v.w);
        uint2 u;
        u.x = *reinterpret_cast<unsigned*>(&h0);
        u.y = *reinterpret_cast<unsigned*>(&h1);
        ((uint2*)dst)[i] = u;
    }
}

// z=0 -> ts cvt, z=1 -> pt cvt, z=2 -> W cvt + ytrues + zero counters
__global__ void k_cvt_all(const float* __restrict__ ts, const float* __restrict__ pt,
                          const float* __restrict__ W1, const float* __restrict__ W2,
                          float* __restrict__ out) {
    const long n4 = 128l * 1024 * 512 / 4;
    const int tid = threadIdx.x;
    if (blockIdx.z == 0) {
        cvt_body(ts, g_ts16, (long)blockIdx.x * 256 + tid, 16384l * 256, n4);
    } else if (blockIdx.z == 1) {
        cvt_body(pt, g_pt16, (long)blockIdx.x * 256 + tid, 16384l * 256, n4);
    } else {
        long x = blockIdx.x;
        if (x < 512) {
            long i = x * 256 + tid;                 // 0..131071 (W1 then W2)
            const float* src = (i < 65536) ? W1 : W2;
            __half* dst = g_w16 + ((i < 65536) ? 0l : 262144l);
            long j = i & 65535;
            float4 v = ((const float4*)src)[j];
            __half2 h0 = __floats2half2_rn(v.x, v.y);
            __half2 h1 = __floats2half2_rn(v.z, v.w);
            uint2 u;
            u.x = *reinterpret_cast<unsigned*>(&h0);
            u.y = *reinterpret_cast<unsigned*>(&h1);
            ((uint2*)dst)[j] = u;
        } else if (x < 1536) {
            long idx = (x - 512) * 256 + tid;
            if (idx < YTRUE_SIZE) out[YTRUE_OFF + idx] = (float)(idx / 2045);
        } else if (x == 1536) {
            if (tid < 2) g_cnt[tid] = 0u;
        }
    }
}

// ---------------- k_pred: R7 core; z = m*2 + step ----------------
// grid (4 cb, 8 l0blk, 256)
__global__ __launch_bounds__(256, 2) void k_pred(const float* __restrict__ b1,
                                                 const float* __restrict__ b2) {
    extern __shared__ char dsm[];
    __shared__ float sb[128];
    const int tid = threadIdx.x;
    const int lane = tid & 31, wid = tid >> 5, wm = wid & 3, wn = wid >> 2;
    const int cb = blockIdx.x;
    const int l0 = blockIdx.y * 128;
    const int step = blockIdx.z & 1;
    const int m = blockIdx.z >> 1;
    const uint32_t base = s2u(dsm);
    const __half* w16 = g_w16 + (long)step * 262144;
    const float* bias = step ? b2 : b1;

    if (tid < 128) sb[tid] = bias[cb * 128 + tid];

    const __half* aP[4]; const __half* bP[4];
#pragma unroll
    for (int i = 0; i < 4; i++) {
        int r = (tid >> 3) + 32 * i;
        aP[i] = g_pt16 + ((long)(m * 1024 + l0 + r)) * 512 + (tid & 7) * 8;
        bP[i] = w16 + ((long)(cb * 128 + r)) * 512 + (tid & 7) * 8;
    }
    const uint32_t seg = (uint32_t)(tid & 7) * 16u;

    auto issue = [&](int kc) {
        uint32_t sbuf = base + (uint32_t)(kc % 3) * STB;
        int koff = kc * 64;
#pragma unroll
        for (int i = 0; i < 4; i++) {
            uint32_t r = (uint32_t)(tid >> 3) + 32u * i;
            cp16(sbuf + r * ROWB + seg, aP[i] + koff);
            cp16(sbuf + MATB + r * ROWB + seg, bP[i] + koff);
        }
    };

    issue(0); CP_COMMIT();
    issue(1); CP_COMMIT();

    float acc[2][8][4] = {};
#pragma unroll
    for (int kc = 0; kc < 8; kc++) {
        if (kc < 7) CP_WAIT1(); else CP_WAIT0();
        __syncthreads();
        if (kc + 2 < 8) { issue(kc + 2); CP_COMMIT(); }
        compute_tile(base + (uint32_t)(kc % 3) * STB,
                     base + (uint32_t)(kc % 3) * STB + MATB, wm, wn, lane, acc);
    }

    // epilogue: +bias, f16 store to g_pred16[step][l0+row][m][cb*128+cl]
#pragma unroll
    for (int mt = 0; mt < 2; mt++) {
        int mrow = wm * 32 + mt * 16 + (lane >> 2);      // l within tile
        long gr = ((long)(step * 1024 + l0 + mrow)) * 128 + m;
#pragma unroll
        for (int nt = 0; nt < 8; nt++) {
            int cl = wn * 64 + nt * 8 + (lane & 3) * 2;
            __half2 h01 = __floats2half2_rn(acc[mt][nt][0] + sb[cl],
                                            acc[mt][nt][1] + sb[cl + 1]);
            *(__half2*)&g_pred16[gr * 512 + cb * 128 + cl] = h01;
            __half2 h23 = __floats2half2_rn(acc[mt][nt][2] + sb[cl],
                                            acc[mt][nt][3] + sb[cl + 1]);
            *(__half2*)&g_pred16[(gr + 8l * 128) * 512 + cb * 128 + cl] = h23;  // l+8
        }
    }
}

// ---------------- k_lneg: 1-D grid paired so same ts column is read by adjacent CTAs ----------------
// z=2k -> (l=k, step=0) reads ts col k+1 ; z=2k+1 -> (l=k-1, step=1) reads ts col k+1
__global__ __launch_bounds__(256, 2) void k_lneg() {
    extern __shared__ char dsm[];
    const int tid = threadIdx.x;
    const int lane = tid & 31, wid = tid >> 5, wm = wid & 3, wn = wid >> 2;
    const int z = blockIdx.x;
    const int step = z & 1;
    const int l = (z >> 1) - step;
    if (l < 0 || l >= 1023 - step) return;   // uniform per CTA
    const uint32_t base = s2u(dsm);

    const __half* aP[4]; const __half* bP[4];
#pragma unroll
    for (int i = 0; i < 4; i++) {
        int r = (tid >> 3) + 32 * i;
        aP[i] = g_ts16 + ((long)(r * 1024) + l + step + 1) * 512 + (tid & 7) * 8;          // n rows
        bP[i] = g_pred16 + (((long)(step * 1024 + l)) * 128 + r) * 512 + (tid & 7) * 8;    // m rows
    }
    const uint32_t seg = (uint32_t)(tid & 7) * 16u;

    auto issue = [&](int kc) {
        uint32_t sbuf = base + (uint32_t)(kc % 3) * STB;
        int koff = kc * 64;
#pragma unroll
        for (int i = 0; i < 4; i++) {
            uint32_t r = (uint32_t)(tid >> 3) + 32u * i;
            cp16(sbuf + r * ROWB + seg, aP[i] + koff);
            cp16(sbuf + MATB + r * ROWB + seg, bP[i] + koff);
        }
    };

    issue(0); CP_COMMIT();
    issue(1); CP_COMMIT();

    float acc[2][8][4] = {};
#pragma unroll
    for (int kc = 0; kc < 8; kc++) {
        if (kc < 7) CP_WAIT1(); else CP_WAIT0();
        __syncthreads();
        if (kc + 2 < 8) { issue(kc + 2); CP_COMMIT(); }
        compute_tile(base + (uint32_t)(kc % 3) * STB,
                     base + (uint32_t)(kc % 3) * STB + MATB, wm, wn, lane, acc);
    }
    __syncthreads();

    float* sC = (float*)dsm;  // [128][129]
#pragma unroll
    for (int mt = 0; mt < 2; mt++) {
        int n = wm * 32 + mt * 16 + (lane >> 2);
#pragma unroll
        for (int nt = 0; nt < 8; nt++) {
            int mc = wn * 64 + nt * 8 + (lane & 3) * 2;
            sC[n * 129 + mc]           = acc[mt][nt][0];
            sC[n * 129 + mc + 1]       = acc[mt][nt][1];
            sC[(n + 8) * 129 + mc]     = acc[mt][nt][2];
            sC[(n + 8) * 129 + mc + 1] = acc[mt][nt][3];
        }
    }
    __syncthreads();

    if (tid < 128) {
        float pos = sC[tid * 129 + tid];
        bool win = true;
#pragma unroll 8
        for (int mm = 0; mm < 128; mm++)
            if (mm != tid && !(pos > sC[tid * 129 + mm])) win = false;
        unsigned bal = __ballot_sync(0xffffffffu, win);
        if ((tid & 31) == 0) atomicAdd(&g_cnt[step], (unsigned)__popc(bal));
    }

    const float invT = 1.0f / 0.07f;
    const long gl = (long)step * 1023 + l;
    for (int idx = tid; idx < 128 * 128; idx += 256) {
        int n = idx >> 7, mm = idx & 127;
        g_lneg[gl * 16384 + idx] = sC[n * 129 + mm] * invT;
    }
}

// ---------------- k_tr: 64x64 tiles; block(0,0) also writes accs ----------------
__global__ __launch_bounds__(256) void k_tr(float* __restrict__ out) {
    __shared__ float t[64][65];
    const int tid = threadIdx.x;
    const int nm0 = blockIdx.x * 64;
    const int gl0 = blockIdx.y * 64;

    if (blockIdx.x == 0 && blockIdx.y == 0) {
        if (tid == 0) out[ACC_OFF + 0] = (float)g_cnt[0] * (1.0f / (128.0f * 1023.0f));
        if (tid == 1) out[ACC_OFF + 1] = (float)g_cnt[1] * (1.0f / (128.0f * 1022.0f));
    }

#pragma unroll
    for (int k = 0; k < 16; k++) {
        int e = tid + k * 256;
        int row = e >> 6, col = e & 63;
        int gl = gl0 + row;
        if (gl < 2045) t[row][col] = g_lneg[(long)gl * 16384 + nm0 + col];
    }
    __syncthreads();
    const int w = tid >> 5, lane = tid & 31;
#pragma unroll
    for (int p = 0; p < 2; p++) {
        int gl = gl0 + p * 32 + lane;
        if (gl < 2045) {
#pragma unroll
            for (int q = 0; q < 8; q++) {
                int nm = w * 8 + q;
                out[(long)(nm0 + nm) * 2045 + gl] = t[p * 32 + lane][nm];
            }
        }
    }
}

// ---------------- launch ----------------
extern "C" void kernel_launch(void* const* d_in, const int* in_sizes, int n_in,
                              void* d_out, int out_size) {
    const float* ts = (const float*)d_in[0];
    const float* pt = (const float*)d_in[1];
    const float* W1 = (const float*)d_in[2];
    const float* b1 = (const float*)d_in[3];
    const float* W2 = (const float*)d_in[4];
    const float* b2 = (const float*)d_in[5];
    float* out = (float*)d_out;

    cudaFuncSetAttribute(k_pred, cudaFuncAttributeMaxDynamicSharedMemorySize, GSMEM);
    cudaFuncSetAttribute(k_lneg, cudaFuncAttributeMaxDynamicSharedMemorySize, GSMEM);

    // prologue: ts cvt (z=0), pt cvt (z=1), W cvt + ytrues + zero (z=2)
    k_cvt_all<<<dim3(16384, 1, 3), 256>>>(ts, pt, W1, W2, out);

    k_pred<<<dim3(4, 8, 256), 256, GSMEM>>>(b1, b2);
    k_lneg<<<2046, 256, GSMEM>>>();
    k_tr<<<dim3(256, 32), 256>>>(out);   // also writes accs
}